// round 9
// baseline (speedup 1.0000x reference)
#include <cuda_runtime.h>
#include <cstdint>

// ---------------------------------------------------------------------------
// Problem constants
// ---------------------------------------------------------------------------
#define TT     16
#define NN     20000
#define NP     20096            // NN padded to multiple of 128 (157*128)
#define NG     32               // 32 (t, graph) pairs total
#define NGP    16               // graph-instances per SAGE pass
#define EE     320000
#define PP     4096
#define DIN    128
#define HH     256
#define NHEAD  8
#define NLAY   2
#define FF     2048
#define DM     512
#define HD     64
#define NTOK   (TT * PP)     // 65536
#define HB     (NGP * NP)    // 321536 rows per SAGE pass (divisible by 256)

// ---------------------------------------------------------------------------
// Scratch blobs (no allocations; keep total .bss < 4GB for aarch64 ADRP).
// ---------------------------------------------------------------------------
constexpr size_t S_H1   = 0;
constexpr size_t S_BUFB = (size_t)HB * 256;
constexpr size_t S_BUFA = S_BUFB;                       // alias (disjoint lifetime)
constexpr size_t S_H2   = 0;                            // alias (disjoint lifetime)
constexpr size_t S_TOTAL= (size_t)HB * 768;             // ~0.99 GB
__device__ float g_sage[S_TOTAL];

// weights region
constexpr size_t W_WC1   = 0;                          // [256,256] stacked fp32
constexpr size_t W_WC2   = W_WC1  + 256ull * 256;      // [512,256]
constexpr size_t W_WQKV  = W_WC2  + 512ull * 256;      // [2,512,1536] tf32-rounded
constexpr size_t W_BQKV  = W_WQKV + 2ull * 512 * 1536; // [2,1536] fp32
constexpr size_t W_WO    = W_BQKV + 2ull * 1536;       // [2,512,512] tf32-rounded
constexpr size_t W_WF1   = W_WO   + 2ull * 512 * 512;  // [2,512,2048] tf32-rounded
constexpr size_t W_WF2   = W_WF1  + 2ull * 512 * 2048; // [2,2048,512] tf32-rounded
constexpr size_t W_TOTAL = W_WF2  + 2ull * 2048 * 512;
__device__ float g_w[W_TOTAL];

// activations region (~1.34 GB)
constexpr size_t A_H    = 0;                           // [NTOK,512]  fp32 hidden
constexpr size_t A_HT   = A_H   + (size_t)NTOK * 512;  // [NTOK,512]  tf32-rounded hidden
constexpr size_t A_QKV  = A_HT  + (size_t)NTOK * 512;  // [NTOK,1536]
constexpr size_t A_TMP  = A_QKV + (size_t)NTOK * 1536; // [NTOK,512]
constexpr size_t A_FF   = A_TMP + (size_t)NTOK * 512;  // [NTOK,2048]
constexpr size_t A_TOTAL= A_FF  + (size_t)NTOK * 2048;
__device__ float g_act[A_TOTAL];

// CSR int region, batched over all NG graphs (~49 MB)
constexpr size_t I_DEG = 0;
constexpr size_t I_CUR = I_DEG + (size_t)NG * NN;
constexpr size_t I_OFF = I_CUR + (size_t)NG * NN;
constexpr size_t I_CSR = I_OFF + (size_t)NG * (NN + 1);
constexpr size_t I_TOTAL = I_CSR + (size_t)NG * EE;
__device__ int g_iblob[I_TOTAL];

// ---------------------------------------------------------------------------
// tf32 helpers
// ---------------------------------------------------------------------------
__device__ __forceinline__ uint32_t f2tf(float f) {
    uint32_t r;
    asm("cvt.rna.tf32.f32 %0, %1;" : "=r"(r) : "f"(f));
    return r;
}

__device__ __forceinline__ void split3(float v, uint32_t& hi, uint32_t& lo) {
    hi = f2tf(v);
    lo = f2tf(v - __uint_as_float(hi));
}

__device__ __forceinline__ void cp16(uint32_t daddr, const void* src) {
    asm volatile("cp.async.cg.shared.global [%0], [%1], 16;" :: "r"(daddr), "l"(src));
}

// ---------------------------------------------------------------------------
// Batched CSR construction (all NG graphs at once).
// ---------------------------------------------------------------------------
__global__ void zero_int_kernel(int* __restrict__ p, int n) {
    int i = blockIdx.x * blockDim.x + threadIdx.x;
    if (i < n) p[i] = 0;
}

__global__ void hist_b_kernel(const int* __restrict__ dst_i, const int* __restrict__ dst_j,
                              int* __restrict__ deg) {
    int gi = blockIdx.y;
    int t = gi & 15, g = gi >> 4;
    const int* dst = (g == 0 ? dst_i : dst_j) + (size_t)t * EE;
    int* d = deg + (size_t)gi * NN;
    int e = blockIdx.x * blockDim.x + threadIdx.x;
    if (e < EE) atomicAdd(&d[dst[e]], 1);
}

__global__ void __launch_bounds__(1024)
scan_b_kernel(const int* __restrict__ deg_all, int* __restrict__ off_all) {
    __shared__ int wsum[32];
    const int CH = 20;
    int gi = blockIdx.x;
    const int* deg = deg_all + (size_t)gi * NN;
    int* off = off_all + (size_t)gi * (NN + 1);
    int tid = threadIdx.x;
    int lane = tid & 31, warp = tid >> 5;
    int base = tid * CH;
    int loc[CH];
    int s = 0;
#pragma unroll
    for (int i = 0; i < CH; i++) {
        int idx = base + i;
        int v = (idx < NN) ? deg[idx] : 0;
        s += v;
        loc[i] = s;
    }
    int ssum = s;
#pragma unroll
    for (int o = 1; o < 32; o <<= 1) {
        int t = __shfl_up_sync(0xffffffffu, ssum, o);
        if (lane >= o) ssum += t;
    }
    if (lane == 31) wsum[warp] = ssum;
    __syncthreads();
    if (warp == 0) {
        int w = wsum[lane];
#pragma unroll
        for (int o = 1; o < 32; o <<= 1) {
            int t = __shfl_up_sync(0xffffffffu, w, o);
            if (lane >= o) w += t;
        }
        wsum[lane] = w;
    }
    __syncthreads();
    int offset = ssum - s + (warp ? wsum[warp - 1] : 0);
    if (tid == 0) off[0] = 0;
#pragma unroll
    for (int i = 0; i < CH; i++) {
        int idx = base + i;
        if (idx < NN) off[idx + 1] = offset + loc[i];
    }
}

__global__ void fill_b_kernel(const int* __restrict__ src_i, const int* __restrict__ src_j,
                              const int* __restrict__ dst_i, const int* __restrict__ dst_j,
                              const int* __restrict__ off_all, int* __restrict__ cur_all,
                              int* __restrict__ csrc_all) {
    int gi = blockIdx.y;
    int t = gi & 15, g = gi >> 4;
    const int* src = (g == 0 ? src_i : src_j) + (size_t)t * EE;
    const int* dst = (g == 0 ? dst_i : dst_j) + (size_t)t * EE;
    const int* off = off_all + (size_t)gi * (NN + 1);
    int* cur = cur_all + (size_t)gi * NN;
    int* csrc = csrc_all + (size_t)gi * EE;
    int e = blockIdx.x * blockDim.x + threadIdx.x;
    if (e < EE) {
        int d = dst[e];
        int p = atomicAdd(&cur[d], 1);
        csrc[off[d] + p] = src[e];
    }
}

// ---------------------------------------------------------------------------
// Per-pass batched build A = [self | mean_agg].  grid (NN, NGP), blockDim = F.
// ---------------------------------------------------------------------------
template <int LAYER>
__global__ void build_A_b_kernel(const float* __restrict__ x, const float* __restrict__ h1,
                                 int F,
                                 const int* __restrict__ off_all, const int* __restrict__ csrc_all,
                                 float* __restrict__ out_all, int gi0) {
    int tl = blockIdx.y;
    int gi = gi0 + tl;
    const float* feat = (LAYER == 1)
        ? (x + (size_t)tl * NN * DIN)
        : (h1 + (size_t)tl * NP * 256);
    const int* off = off_all + (size_t)gi * (NN + 1);
    const int* csrc = csrc_all + (size_t)gi * EE;
    float* out = out_all + (size_t)tl * NP * (2 * F);

    int n = blockIdx.x;
    int f = threadIdx.x;
    float self = feat[(size_t)n * F + f];
    int s = off[n], e = off[n + 1];
    float acc = 0.f;
    int i = s;
    for (; i + 4 <= e; i += 4) {
        int a0 = csrc[i], a1 = csrc[i + 1], a2 = csrc[i + 2], a3 = csrc[i + 3];
        float v0 = feat[(size_t)a0 * F + f];
        float v1 = feat[(size_t)a1 * F + f];
        float v2 = feat[(size_t)a2 * F + f];
        float v3 = feat[(size_t)a3 * F + f];
        acc += v0 + v1 + v2 + v3;
    }
    for (; i < e; i++) acc += feat[(size_t)csrc[i] * F + f];
    int d = e - s; if (d < 1) d = 1;
    size_t ob = (size_t)n * (2 * F);
    out[ob + f]     = self;
    out[ob + F + f] = acc / (float)d;
}

// ---------------------------------------------------------------------------
// TF32 tensor-core GEMM.  C = A@B + bias (+relu).
// 256x128x16 block tile, 256 threads = 8 warps as 4(m) x 2(n),
// warp tile 64x64, mma.sync.m16n8k8.tf32, cp.async double-buffered.
// Dynamic smem (58368 B).  M % 256 == 0, N % 128 == 0, K % 16 == 0.
// X3    : 3xTF32 split (fp32-comparable accuracy) — SAGE path.
// PRE   : operands already tf32-rounded in gmem — no cvt in hot loop.
// OROUND: round C store to tf32 bits (feeds a later PRE GEMM).
// ---------------------------------------------------------------------------
#define AS_STRIDE 20
#define BS_STRIDE 136
#define GEMM_SMEM_BYTES ((2 * 256 * AS_STRIDE + 2 * 16 * BS_STRIDE) * 4)

#define MMA_TF32(d, a, b)                                                            \
    asm volatile(                                                                    \
        "mma.sync.aligned.m16n8k8.row.col.f32.tf32.tf32.f32 "                        \
        "{%0,%1,%2,%3},{%4,%5,%6,%7},{%8,%9},{%0,%1,%2,%3};"                         \
        : "+f"(d[0]), "+f"(d[1]), "+f"(d[2]), "+f"(d[3])                             \
        : "r"(a[0]), "r"(a[1]), "r"(a[2]), "r"(a[3]), "r"(b[0]), "r"(b[1]))

template <int RELU, int X3, int PRE, int OROUND>
__global__ void __launch_bounds__(256, 1)
tf32_gemm_kernel(const float* __restrict__ A, const float* __restrict__ B,
                 const float* __restrict__ bias, float* __restrict__ C,
                 int M, int K, int N) {
    extern __shared__ float smem[];
    // As[2][256][AS_STRIDE], Bs[2][16][BS_STRIDE]
    float* AsBase = smem;
    float* BsBase = smem + 2 * 256 * AS_STRIDE;
#define AS(st, r, c) AsBase[((st) * 256 + (r)) * AS_STRIDE + (c)]
#define BS(st, r, c) BsBase[((st) * 16 + (r)) * BS_STRIDE + (c)]

    int tid  = threadIdx.x;
    int warp = tid >> 5;
    int lane = tid & 31;
    int gid  = lane >> 2;
    int tq   = lane & 3;
    int wm   = warp >> 1;   // 0..3  -> 64-row slice
    int wn   = warp & 1;    // 0..1  -> 64-col slice

    int bm = blockIdx.y * 256;
    int bn = blockIdx.x * 128;

    float acc[4][8][4];
#pragma unroll
    for (int i = 0; i < 4; i++)
#pragma unroll
        for (int j = 0; j < 8; j++)
#pragma unroll
            for (int r = 0; r < 4; r++) acc[i][j][r] = 0.f;

    int nk = K >> 4;

    const float* Abase = A + (size_t)bm * K;
    const float* Bbase = B + bn;

    auto load_stage = [&](int stage, int k0) {
#pragma unroll
        for (int it = 0; it < 4; it++) {                   // A: 256x16 = 1024 float4
            int i = tid + it * 256;
            int row = i >> 2, c4 = (i & 3) << 2;
            uint32_t d = (uint32_t)__cvta_generic_to_shared(&AS(stage, row, c4));
            cp16(d, Abase + (size_t)row * K + k0 + c4);
        }
#pragma unroll
        for (int it = 0; it < 2; it++) {                   // B: 16x128 = 512 float4
            int i = tid + it * 256;
            int row = i >> 5, c4 = (i & 31) << 2;
            uint32_t d = (uint32_t)__cvta_generic_to_shared(&BS(stage, row, c4));
            cp16(d, Bbase + (size_t)(k0 + row) * N + c4);
        }
    };

    load_stage(0, 0);
    asm volatile("cp.async.commit_group;");

    for (int kc = 0; kc < nk; kc++) {
        int cur = kc & 1;
        if (kc + 1 < nk) {
            load_stage(cur ^ 1, (kc + 1) << 4);
            asm volatile("cp.async.commit_group;");
            asm volatile("cp.async.wait_group 1;");
        } else {
            asm volatile("cp.async.wait_group 0;");
        }
        __syncthreads();

#pragma unroll
        for (int ks = 0; ks < 16; ks += 8) {
            uint32_t af[4][4], bf[8][2];
            uint32_t afl[4][4], bfl[8][2];
#pragma unroll
            for (int mt = 0; mt < 4; mt++) {
                int m = wm * 64 + mt * 16;
                float v0 = AS(cur, m + gid,     ks + tq);
                float v1 = AS(cur, m + gid + 8, ks + tq);
                float v2 = AS(cur, m + gid,     ks + tq + 4);
                float v3 = AS(cur, m + gid + 8, ks + tq + 4);
                if (X3) {
                    split3(v0, af[mt][0], afl[mt][0]);
                    split3(v1, af[mt][1], afl[mt][1]);
                    split3(v2, af[mt][2], afl[mt][2]);
                    split3(v3, af[mt][3], afl[mt][3]);
                } else if (PRE) {
                    af[mt][0] = __float_as_uint(v0); af[mt][1] = __float_as_uint(v1);
                    af[mt][2] = __float_as_uint(v2); af[mt][3] = __float_as_uint(v3);
                } else {
                    af[mt][0] = f2tf(v0); af[mt][1] = f2tf(v1);
                    af[mt][2] = f2tf(v2); af[mt][3] = f2tf(v3);
                }
            }
#pragma unroll
            for (int nt = 0; nt < 8; nt++) {
                int n = wn * 64 + nt * 8;
                float u0 = BS(cur, ks + tq,     n + gid);
                float u1 = BS(cur, ks + tq + 4, n + gid);
                if (X3) {
                    split3(u0, bf[nt][0], bfl[nt][0]);
                    split3(u1, bf[nt][1], bfl[nt][1]);
                } else if (PRE) {
                    bf[nt][0] = __float_as_uint(u0); bf[nt][1] = __float_as_uint(u1);
                } else {
                    bf[nt][0] = f2tf(u0); bf[nt][1] = f2tf(u1);
                }
            }
#pragma unroll
            for (int mt = 0; mt < 4; mt++)
#pragma unroll
                for (int nt = 0; nt < 8; nt++) {
                    MMA_TF32(acc[mt][nt], af[mt], bf[nt]);
                    if (X3) {
                        MMA_TF32(acc[mt][nt], af[mt], bfl[nt]);
                        MMA_TF32(acc[mt][nt], afl[mt], bf[nt]);
                    }
                }
        }
        __syncthreads();
    }

#pragma unroll
    for (int mt = 0; mt < 4; mt++) {
        int gr = bm + wm * 64 + mt * 16 + gid;
#pragma unroll
        for (int nt = 0; nt < 8; nt++) {
            int gc = bn + wn * 64 + nt * 8 + tq * 2;
            float2 bv = *(const float2*)&bias[gc];
            float v0 = acc[mt][nt][0] + bv.x;
            float v1 = acc[mt][nt][1] + bv.y;
            float v2 = acc[mt][nt][2] + bv.x;
            float v3 = acc[mt][nt][3] + bv.y;
            if (RELU) {
                v0 = fmaxf(v0, 0.f); v1 = fmaxf(v1, 0.f);
                v2 = fmaxf(v2, 0.f); v3 = fmaxf(v3, 0.f);
            }
            if (OROUND) {
                v0 = __uint_as_float(f2tf(v0)); v1 = __uint_as_float(f2tf(v1));
                v2 = __uint_as_float(f2tf(v2)); v3 = __uint_as_float(f2tf(v3));
            }
            *(float2*)&C[(size_t)gr * N + gc]       = make_float2(v0, v1);
            *(float2*)&C[(size_t)(gr + 8) * N + gc] = make_float2(v2, v3);
        }
    }
#undef AS
#undef BS
}

// ---------------------------------------------------------------------------
// Per-pass gather + L2-normalize.  grid (PP, NGP), block 256.
// ---------------------------------------------------------------------------
__global__ void gather_norm_b_kernel(const float* __restrict__ h2_all,
                                     const int* __restrict__ idx_base,
                                     float* __restrict__ att_out, float* __restrict__ h,
                                     float* __restrict__ h_t, int g) {
    int t = blockIdx.y;
    const int* idx = idx_base + (size_t)t * PP;
    const float* h2 = h2_all + (size_t)t * NP * 256;

    int p = blockIdx.x;
    int f = threadIdx.x;
    int n = idx[p];
    float v = h2[(size_t)n * 256 + f];
    float s = v * v;
    __shared__ float red[8];
    for (int o = 16; o; o >>= 1) s += __shfl_xor_sync(0xffffffffu, s, o);
    if ((f & 31) == 0) red[f >> 5] = s;
    __syncthreads();
    float tot = red[0] + red[1] + red[2] + red[3] + red[4] + red[5] + red[6] + red[7];
    float norm = fmaxf(sqrtf(tot), 1e-12f);
    v /= norm;
    size_t o = ((size_t)(t * PP + p)) * DM + g * 256 + f;
    att_out[o] = v;
    h[o]       = v;
    h_t[o]     = __uint_as_float(f2tf(v));
}

// ---------------------------------------------------------------------------
// Banded attention: window 4, T=16.  One block per (p, head), 128 threads.
// float4 smem fill; output tf32-rounded (feeds PRE Wo GEMM).
// ---------------------------------------------------------------------------
__global__ void attn_kernel(const float* __restrict__ qkv, float* __restrict__ out) {
    int ph = blockIdx.x;
    int p = ph >> 3;
    int h = ph & 7;
    __shared__ float qs[16][64], ks[16][64], vs[16][64];
    int tid = threadIdx.x;
    // 16 rows x 64 floats = 256 float4 per array; 2 per thread per array
    for (int i = tid; i < 256; i += 128) {
        int t = i >> 4, d4 = (i & 15) << 2;
        const float4* b = (const float4*)(qkv + ((size_t)(t * PP + p)) * 1536 + h * 64 + d4);
        *(float4*)&qs[t][d4] = b[0];
        *(float4*)&ks[t][d4] = b[128];   // +512 floats
        *(float4*)&vs[t][d4] = b[256];   // +1024 floats
    }
    __syncthreads();
    int warp = tid >> 5, lane = tid & 31;
    for (int t = warp; t < 16; t += 4) {
        int s0 = t - 3; if (s0 < 0) s0 = 0;
        int ns = t - s0 + 1;
        float sc[4];
        float mx = -1e30f;
        for (int si = 0; si < ns; si++) {
            int s = s0 + si;
            float d0 = qs[t][lane] * ks[s][lane] + qs[t][lane + 32] * ks[s][lane + 32];
            for (int o = 16; o; o >>= 1) d0 += __shfl_xor_sync(0xffffffffu, d0, o);
            d0 *= 0.125f;
            sc[si] = d0;
            mx = fmaxf(mx, d0);
        }
        float sum = 0.f;
        for (int si = 0; si < ns; si++) { sc[si] = expf(sc[si] - mx); sum += sc[si]; }
        float inv = 1.f / sum;
        float o0 = 0.f, o1 = 0.f;
        for (int si = 0; si < ns; si++) {
            int s = s0 + si;
            o0 += sc[si] * vs[s][lane];
            o1 += sc[si] * vs[s][lane + 32];
        }
        size_t ob = ((size_t)(t * PP + p)) * DM + h * 64;
        out[ob + lane]      = __uint_as_float(f2tf(o0 * inv));
        out[ob + lane + 32] = __uint_as_float(f2tf(o1 * inv));
    }
}

// ---------------------------------------------------------------------------
// h = LayerNorm(h + delta) * g + b; also emits tf32-rounded copy h_t.
// ---------------------------------------------------------------------------
__global__ void resid_ln_kernel(float* __restrict__ h, const float* __restrict__ delta,
                                const float* __restrict__ g, const float* __restrict__ b,
                                float* __restrict__ h_t) {
    int row = blockIdx.x;
    int tid = threadIdx.x;
    size_t base = (size_t)row * DM;
    float v[4];
    float s = 0.f;
#pragma unroll
    for (int i = 0; i < 4; i++) {
        int c = tid + i * 128;
        float x = h[base + c] + delta[base + c];
        v[i] = x; s += x;
    }
    __shared__ float red[4];
    for (int o = 16; o; o >>= 1) s += __shfl_xor_sync(0xffffffffu, s, o);
    if ((tid & 31) == 0) red[tid >> 5] = s;
    __syncthreads();
    float mean = (red[0] + red[1] + red[2] + red[3]) * (1.f / 512.f);
    __syncthreads();
    float s2 = 0.f;
#pragma unroll
    for (int i = 0; i < 4; i++) { float d = v[i] - mean; s2 += d * d; }
    for (int o = 16; o; o >>= 1) s2 += __shfl_xor_sync(0xffffffffu, s2, o);
    if ((tid & 31) == 0) red[tid >> 5] = s2;
    __syncthreads();
    float var = (red[0] + red[1] + red[2] + red[3]) * (1.f / 512.f);
    float rstd = rsqrtf(var + 1e-5f);
#pragma unroll
    for (int i = 0; i < 4; i++) {
        int c = tid + i * 128;
        float o = (v[i] - mean) * rstd * g[c] + b[c];
        h[base + c]   = o;
        h_t[base + c] = __uint_as_float(f2tf(o));
    }
}

// Final projection: out[tok] = h[tok,:] . Wout.  Warp per token.
__global__ void out_kernel(const float* __restrict__ h, const float* __restrict__ W,
                           float* __restrict__ out) {
    int tok = blockIdx.x * 8 + (threadIdx.x >> 5);
    int lane = threadIdx.x & 31;
    const float* r = h + (size_t)tok * DM;
    float s = 0.f;
#pragma unroll
    for (int i = 0; i < 16; i++) s += r[lane + i * 32] * W[lane + i * 32];
    for (int o = 16; o; o >>= 1) s += __shfl_xor_sync(0xffffffffu, s, o);
    if (lane == 0) out[tok] = s;
}

// ---------------------------------------------------------------------------
// Weight prep
// ---------------------------------------------------------------------------
__global__ void prep_wc_kernel(const float* __restrict__ W1s, const float* __restrict__ W1n,
                               const float* __restrict__ W2s, const float* __restrict__ W2n,
                               float* __restrict__ wc1, float* __restrict__ wc2) {
    int i = blockIdx.x * blockDim.x + threadIdx.x;
    if (i < 256 * 256) {
        int k = i >> 8, c = i & 255;
        wc1[i] = (k < 128) ? W1s[k * 256 + c] : W1n[(k - 128) * 256 + c];
    }
    if (i < 512 * 256) {
        int k = i >> 8, c = i & 255;
        wc2[i] = (k < 256) ? W2s[k * 256 + c] : W2n[(k - 256) * 256 + c];
    }
}

__global__ void prep_wqkv_kernel(const float* __restrict__ Wq, const float* __restrict__ Wk,
                                 const float* __restrict__ Wv,
                                 const float* __restrict__ bq, const float* __restrict__ bk,
                                 const float* __restrict__ bv,
                                 float* __restrict__ Wqkv, float* __restrict__ bqkv) {
    int i = blockIdx.x * blockDim.x + threadIdx.x;
    const int tot = 2 * 512 * 1536;
    if (i < tot) {
        int l = i / (512 * 1536);
        int rem = i % (512 * 1536);
        int r = rem / 1536, c = rem % 1536;
        float v;
        size_t wb = (size_t)l * 512 * 512 + (size_t)r * 512;
        if (c < 512)       v = Wq[wb + c];
        else if (c < 1024) v = Wk[wb + (c - 512)];
        else               v = Wv[wb + (c - 1024)];
        Wqkv[i] = __uint_as_float(f2tf(v));
    }
    if (i < 2 * 1536) {
        int l = i / 1536, c = i % 1536;
        float v;
        if (c < 512)       v = bq[l * 512 + c];
        else if (c < 1024) v = bk[l * 512 + c - 512];
        else               v = bv[l * 512 + c - 1024];
        bqkv[i] = v;
    }
}

__global__ void prep_round_kernel(const float* __restrict__ Wo, const float* __restrict__ Wf1,
                                  const float* __restrict__ Wf2,
                                  float* __restrict__ wo_t, float* __restrict__ wf1_t,
                                  float* __restrict__ wf2_t) {
    const int NWO  = 2 * 512 * 512;
    const int NWF1 = 2 * 512 * 2048;
    const int NWF2 = 2 * 2048 * 512;
    int i = blockIdx.x * blockDim.x + threadIdx.x;
    if (i < NWO)  wo_t[i]  = __uint_as_float(f2tf(Wo[i]));
    if (i < NWF1) wf1_t[i] = __uint_as_float(f2tf(Wf1[i]));
    if (i < NWF2) wf2_t[i] = __uint_as_float(f2tf(Wf2[i]));
}

// ---------------------------------------------------------------------------
// Host driver
// ---------------------------------------------------------------------------
extern "C" void kernel_launch(void* const* d_in, const int* in_sizes, int n_in,
                              void* d_out, int out_size) {
    const float* x_i   = (const float*)d_in[0];
    const float* x_j   = (const float*)d_in[1];
    const int*   src_i = (const int*)d_in[2];
    const int*   dst_i = (const int*)d_in[3];
    const int*   src_j = (const int*)d_in[4];
    const int*   dst_j = (const int*)d_in[5];
    const int*   idx_i = (const int*)d_in[6];
    const int*   idx_j = (const int*)d_in[7];
    const float* W1s = (const float*)d_in[8];
    const float* W1n = (const float*)d_in[9];
    const float* b1  = (const float*)d_in[10];
    const float* W2s = (const float*)d_in[11];
    const float* W2n = (const float*)d_in[12];
    const float* b2  = (const float*)d_in[13];
    const float* Wq  = (const float*)d_in[14];
    const float* Wk  = (const float*)d_in[15];
    const float* Wv  = (const float*)d_in[16];
    const float* bq  = (const float*)d_in[17];
    const float* bk  = (const float*)d_in[18];
    const float* bv  = (const float*)d_in[19];
    const float* Wo  = (const float*)d_in[20];
    const float* bo  = (const float*)d_in[21];
    const float* Wf1 = (const float*)d_in[22];
    const float* bf1 = (const float*)d_in[23];
    const float* Wf2 = (const float*)d_in[24];
    const float* bf2 = (const float*)d_in[25];
    const float* g1  = (const float*)d_in[26];
    const float* bg1 = (const float*)d_in[27];
    const float* g2  = (const float*)d_in[28];
    const float* bg2 = (const float*)d_in[29];
    const float* Wout= (const float*)d_in[30];

    void* p;
    cudaGetSymbolAddress(&p, g_sage);  float* SB = (float*)p;
    cudaGetSymbolAddress(&p, g_w);     float* WB = (float*)p;
    cudaGetSymbolAddress(&p, g_act);   float* AB = (float*)p;
    cudaGetSymbolAddress(&p, g_iblob); int*   IB = (int*)p;

    float* h1   = SB + S_H1;
    float* bufB = SB + S_BUFB;
    float* bufA = SB + S_BUFA;
    float* h2   = SB + S_H2;

    float* wc1   = WB + W_WC1;
    float* wc2   = WB + W_WC2;
    float* wqkv  = WB + W_WQKV;
    float* bqkv  = WB + W_BQKV;
    float* wo_t  = WB + W_WO;
    float* wf1_t = WB + W_WF1;
    float* wf2_t = WB + W_WF2;

    float* hbuf = AB + A_H;
    float* h_t  = AB + A_HT;
    float* qkv  = AB + A_QKV;
    float* tmp  = AB + A_TMP;
    float* ffb  = AB + A_FF;

    int* deg  = IB + I_DEG;
    int* cur  = IB + I_CUR;
    int* off  = IB + I_OFF;
    int* csrc = IB + I_CSR;

    float* att_out  = (float*)d_out;
    float* scal_out = att_out + (size_t)NTOK * DM;

    // opt-in to >48KB dynamic smem for each GEMM instantiation (host-side, capture-safe)
    cudaFuncSetAttribute(tf32_gemm_kernel<1, 1, 0, 0>,
                         cudaFuncAttributeMaxDynamicSharedMemorySize, GEMM_SMEM_BYTES);
    cudaFuncSetAttribute(tf32_gemm_kernel<0, 1, 0, 0>,
                         cudaFuncAttributeMaxDynamicSharedMemorySize, GEMM_SMEM_BYTES);
    cudaFuncSetAttribute(tf32_gemm_kernel<0, 0, 1, 0>,
                         cudaFuncAttributeMaxDynamicSharedMemorySize, GEMM_SMEM_BYTES);
    cudaFuncSetAttribute(tf32_gemm_kernel<1, 0, 1, 1>,
                         cudaFuncAttributeMaxDynamicSharedMemorySize, GEMM_SMEM_BYTES);

    // ---- weight prep ----
    prep_wc_kernel<<<(512 * 256 + 255) / 256, 256>>>(W1s, W1n, W2s, W2n, wc1, wc2);
    prep_wqkv_kernel<<<(2 * 512 * 1536 + 255) / 256, 256>>>(Wq, Wk, Wv, bq, bk, bv, wqkv, bqkv);
    prep_round_kernel<<<(2 * 512 * 2048 + 255) / 256, 256>>>(Wo, Wf1, Wf2, wo_t, wf1_t, wf2_t);

    // ---- batched CSR for all NG graphs ----
    zero_int_kernel<<<(2 * NG * NN + 255) / 256, 256>>>(IB, 2 * NG * NN);
    hist_b_kernel<<<dim3((EE + 255) / 256, NG), 256>>>(dst_i, dst_j, deg);
    scan_b_kernel<<<NG, 1024>>>(deg, off);
    fill_b_kernel<<<dim3((EE + 255) / 256, NG), 256>>>(src_i, src_j, dst_i, dst_j, off, cur, csrc);

    // ---- batched GraphSAGE, 2 passes ----
    for (int g = 0; g < 2; g++) {
        const float* x   = (g == 0) ? x_i : x_j;
        const int*   idx = (g == 0) ? idx_i : idx_j;
        int gi0 = g * NGP;
        build_A_b_kernel<1><<<dim3(NN, NGP), 128>>>(x, nullptr, 128, off, csrc, bufA, gi0);
        tf32_gemm_kernel<1, 1, 0, 0><<<dim3(2, HB / 256), 256, GEMM_SMEM_BYTES>>>(
            bufA, wc1, b1, h1, HB, 256, 256);
        build_A_b_kernel<2><<<dim3(NN, NGP), 256>>>(nullptr, h1, 256, off, csrc, bufB, gi0);
        tf32_gemm_kernel<0, 1, 0, 0><<<dim3(2, HB / 256), 256, GEMM_SMEM_BYTES>>>(
            bufB, wc2, b2, h2, HB, 512, 256);
        gather_norm_b_kernel<<<dim3(PP, NGP), 256>>>(h2, idx, att_out, hbuf, h_t, g);
    }

    // ---- Transformer (PRE tf32 tensor-core GEMMs) ----
    for (int l = 0; l < NLAY; l++) {
        tf32_gemm_kernel<0, 0, 1, 0><<<dim3(12, NTOK / 256), 256, GEMM_SMEM_BYTES>>>(
            h_t, wqkv + (size_t)l * 512 * 1536, bqkv + l * 1536, qkv, NTOK, 512, 1536);
        attn_kernel<<<PP * NHEAD, 128>>>(qkv, tmp);
        tf32_gemm_kernel<0, 0, 1, 0><<<dim3(4, NTOK / 256), 256, GEMM_SMEM_BYTES>>>(
            tmp, wo_t + (size_t)l * 512 * 512, bo + l * 512, ffb, NTOK, 512, 512);
        resid_ln_kernel<<<NTOK, 128>>>(hbuf, ffb, g1 + l * 512, bg1 + l * 512, h_t);
        tf32_gemm_kernel<1, 0, 1, 1><<<dim3(16, NTOK / 256), 256, GEMM_SMEM_BYTES>>>(
            h_t, wf1_t + (size_t)l * 512 * 2048, bf1 + l * 2048, ffb, NTOK, 512, 2048);
        tf32_gemm_kernel<0, 0, 1, 0><<<dim3(4, NTOK / 256), 256, GEMM_SMEM_BYTES>>>(
            ffb, wf2_t + (size_t)l * 2048 * 512, bf2 + l * 512, tmp, NTOK, 2048, 512);
        resid_ln_kernel<<<NTOK, 128>>>(hbuf, tmp, g2 + l * 512, bg2 + l * 512, h_t);
    }

    out_kernel<<<NTOK / 8, 256>>>(hbuf, Wout, scal_out);
}

// round 10
// speedup vs baseline: 1.1372x; 1.1372x over previous
#include <cuda_runtime.h>
#include <cstdint>

// ---------------------------------------------------------------------------
// Problem constants
// ---------------------------------------------------------------------------
#define TT     16
#define NN     20000
#define NP     20096            // NN padded to multiple of 128 (157*128)
#define NG     32               // 32 (t, graph) pairs total
#define NGP    16               // graph-instances per SAGE pass
#define EE     320000
#define PP     4096
#define DIN    128
#define HH     256
#define NHEAD  8
#define NLAY   2
#define FF     2048
#define DM     512
#define HD     64
#define NTOK   (TT * PP)     // 65536
#define HB     (NGP * NP)    // 321536 rows per SAGE pass

// ---------------------------------------------------------------------------
// Scratch blobs (no allocations; keep total .bss < 4GB for aarch64 ADRP).
// ---------------------------------------------------------------------------
constexpr size_t S_H1   = 0;
constexpr size_t S_BUFB = (size_t)HB * 256;
constexpr size_t S_BUFA = S_BUFB;                       // alias (disjoint lifetime)
constexpr size_t S_H2   = 0;                            // alias (disjoint lifetime)
constexpr size_t S_TOTAL= (size_t)HB * 768;             // ~0.99 GB
__device__ float g_sage[S_TOTAL];

// weights region
constexpr size_t W_WC1   = 0;                          // [256,256] stacked fp32
constexpr size_t W_WC2   = W_WC1  + 256ull * 256;      // [512,256]
constexpr size_t W_WQKV  = W_WC2  + 512ull * 256;      // [2,512,1536] tf32-rounded
constexpr size_t W_BQKV  = W_WQKV + 2ull * 512 * 1536; // [2,1536] fp32
constexpr size_t W_WO    = W_BQKV + 2ull * 1536;       // [2,512,512] tf32-rounded
constexpr size_t W_WF1   = W_WO   + 2ull * 512 * 512;  // [2,512,2048] tf32-rounded
constexpr size_t W_WF2   = W_WF1  + 2ull * 512 * 2048; // [2,2048,512] tf32-rounded
constexpr size_t W_TOTAL = W_WF2  + 2ull * 2048 * 512;
__device__ float g_w[W_TOTAL];

// activations region (~1.34 GB)
constexpr size_t A_H    = 0;                           // [NTOK,512]  fp32 hidden
constexpr size_t A_HT   = A_H   + (size_t)NTOK * 512;  // [NTOK,512]  tf32-rounded hidden
constexpr size_t A_QKV  = A_HT  + (size_t)NTOK * 512;  // [NTOK,1536]
constexpr size_t A_TMP  = A_QKV + (size_t)NTOK * 1536; // [NTOK,512]
constexpr size_t A_FF   = A_TMP + (size_t)NTOK * 512;  // [NTOK,2048]
constexpr size_t A_TOTAL= A_FF  + (size_t)NTOK * 2048;
__device__ float g_act[A_TOTAL];

// CSR int region, batched over all NG graphs (~49 MB)
constexpr size_t I_DEG = 0;
constexpr size_t I_CUR = I_DEG + (size_t)NG * NN;
constexpr size_t I_OFF = I_CUR + (size_t)NG * NN;
constexpr size_t I_CSR = I_OFF + (size_t)NG * (NN + 1);
constexpr size_t I_TOTAL = I_CSR + (size_t)NG * EE;
__device__ int g_iblob[I_TOTAL];

// ---------------------------------------------------------------------------
// numeric helpers
// ---------------------------------------------------------------------------
__device__ __forceinline__ uint32_t f2tf(float f) {
    uint32_t r;
    asm("cvt.rna.tf32.f32 %0, %1;" : "=r"(r) : "f"(f));
    return r;
}

// pack (v0 -> low bf16, v1 -> high bf16) and the bf16 split remainders
__device__ __forceinline__ void bf16_split_pack(float v0, float v1,
                                                uint32_t& hi, uint32_t& lo) {
    uint32_t h;
    asm("cvt.rn.bf16x2.f32 %0, %1, %2;" : "=r"(h) : "f"(v1), "f"(v0));
    float h0 = __uint_as_float(h << 16);
    float h1 = __uint_as_float(h & 0xFFFF0000u);
    hi = h;
    asm("cvt.rn.bf16x2.f32 %0, %1, %2;" : "=r"(lo) : "f"(v1 - h1), "f"(v0 - h0));
}

__device__ __forceinline__ void cp16(uint32_t daddr, const void* src) {
    asm volatile("cp.async.cg.shared.global [%0], [%1], 16;" :: "r"(daddr), "l"(src));
}

// ---------------------------------------------------------------------------
// Batched CSR construction (all NG graphs at once).
// ---------------------------------------------------------------------------
__global__ void hist_b_kernel(const int* __restrict__ dst_i, const int* __restrict__ dst_j,
                              int* __restrict__ deg) {
    int gi = blockIdx.y;
    int t = gi & 15, g = gi >> 4;
    const int* dst = (g == 0 ? dst_i : dst_j) + (size_t)t * EE;
    int* d = deg + (size_t)gi * NN;
    int e = blockIdx.x * blockDim.x + threadIdx.x;
    if (e < EE) atomicAdd(&d[dst[e]], 1);
}

__global__ void __launch_bounds__(1024)
scan_b_kernel(const int* __restrict__ deg_all, int* __restrict__ off_all) {
    __shared__ int wsum[32];
    const int CH = 20;
    int gi = blockIdx.x;
    const int* deg = deg_all + (size_t)gi * NN;
    int* off = off_all + (size_t)gi * (NN + 1);
    int tid = threadIdx.x;
    int lane = tid & 31, warp = tid >> 5;
    int base = tid * CH;
    int loc[CH];
    int s = 0;
#pragma unroll
    for (int i = 0; i < CH; i++) {
        int idx = base + i;
        int v = (idx < NN) ? deg[idx] : 0;
        s += v;
        loc[i] = s;
    }
    int ssum = s;
#pragma unroll
    for (int o = 1; o < 32; o <<= 1) {
        int t = __shfl_up_sync(0xffffffffu, ssum, o);
        if (lane >= o) ssum += t;
    }
    if (lane == 31) wsum[warp] = ssum;
    __syncthreads();
    if (warp == 0) {
        int w = wsum[lane];
#pragma unroll
        for (int o = 1; o < 32; o <<= 1) {
            int t = __shfl_up_sync(0xffffffffu, w, o);
            if (lane >= o) w += t;
        }
        wsum[lane] = w;
    }
    __syncthreads();
    int offset = ssum - s + (warp ? wsum[warp - 1] : 0);
    if (tid == 0) off[0] = 0;
#pragma unroll
    for (int i = 0; i < CH; i++) {
        int idx = base + i;
        if (idx < NN) off[idx + 1] = offset + loc[i];
    }
}

__global__ void fill_b_kernel(const int* __restrict__ src_i, const int* __restrict__ src_j,
                              const int* __restrict__ dst_i, const int* __restrict__ dst_j,
                              const int* __restrict__ off_all, int* __restrict__ cur_all,
                              int* __restrict__ csrc_all) {
    int gi = blockIdx.y;
    int t = gi & 15, g = gi >> 4;
    const int* src = (g == 0 ? src_i : src_j) + (size_t)t * EE;
    const int* dst = (g == 0 ? dst_i : dst_j) + (size_t)t * EE;
    const int* off = off_all + (size_t)gi * (NN + 1);
    int* cur = cur_all + (size_t)gi * NN;
    int* csrc = csrc_all + (size_t)gi * EE;
    int e = blockIdx.x * blockDim.x + threadIdx.x;
    if (e < EE) {
        int d = dst[e];
        int p = atomicAdd(&cur[d], 1);
        csrc[off[d] + p] = src[e];
    }
}

// ---------------------------------------------------------------------------
// Per-pass batched build A = [self | mean_agg].  grid (NN, NGP), blockDim = F.
// ---------------------------------------------------------------------------
template <int LAYER>
__global__ void build_A_b_kernel(const float* __restrict__ x, const float* __restrict__ h1,
                                 int F,
                                 const int* __restrict__ off_all, const int* __restrict__ csrc_all,
                                 float* __restrict__ out_all, int gi0) {
    int tl = blockIdx.y;
    int gi = gi0 + tl;
    const float* feat = (LAYER == 1)
        ? (x + (size_t)tl * NN * DIN)
        : (h1 + (size_t)tl * NP * 256);
    const int* off = off_all + (size_t)gi * (NN + 1);
    const int* csrc = csrc_all + (size_t)gi * EE;
    float* out = out_all + (size_t)tl * NP * (2 * F);

    int n = blockIdx.x;
    int f = threadIdx.x;
    float self = feat[(size_t)n * F + f];
    int s = off[n], e = off[n + 1];
    float acc = 0.f;
    int i = s;
    for (; i + 4 <= e; i += 4) {
        int a0 = csrc[i], a1 = csrc[i + 1], a2 = csrc[i + 2], a3 = csrc[i + 3];
        float v0 = feat[(size_t)a0 * F + f];
        float v1 = feat[(size_t)a1 * F + f];
        float v2 = feat[(size_t)a2 * F + f];
        float v3 = feat[(size_t)a3 * F + f];
        acc += v0 + v1 + v2 + v3;
    }
    for (; i < e; i++) acc += feat[(size_t)csrc[i] * F + f];
    int d = e - s; if (d < 1) d = 1;
    size_t ob = (size_t)n * (2 * F);
    out[ob + f]     = self;
    out[ob + F + f] = acc / (float)d;
}

// ---------------------------------------------------------------------------
// Tensor-core GEMM.  C = A@B + bias (+relu).  128x128x16 block tile,
// 256 threads = 8 warps as 2(m) x 4(n), warp tile 64x32, cp.async dbl-buffered.
// BF16S : bf16 2-way-split (hi/lo) path, 3x m16n8k16 per chunk — SAGE
//         (fp32-comparable accuracy, half the tensor cycles of 3xTF32).
// PRE   : operands already tf32-rounded in gmem — m16n8k8 tf32, no cvt.
// OROUND: round C store to tf32 bits (feeds a later PRE GEMM).
// M,N multiples of 128, K multiple of 16.
// ---------------------------------------------------------------------------
#define AS_STRIDE 20
#define BS_STRIDE 136

#define MMA_TF32(d, a, b)                                                            \
    asm volatile(                                                                    \
        "mma.sync.aligned.m16n8k8.row.col.f32.tf32.tf32.f32 "                        \
        "{%0,%1,%2,%3},{%4,%5,%6,%7},{%8,%9},{%0,%1,%2,%3};"                         \
        : "+f"(d[0]), "+f"(d[1]), "+f"(d[2]), "+f"(d[3])                             \
        : "r"(a[0]), "r"(a[1]), "r"(a[2]), "r"(a[3]), "r"(b[0]), "r"(b[1]))

#define MMA_BF16(d, a, b)                                                            \
    asm volatile(                                                                    \
        "mma.sync.aligned.m16n8k16.row.col.f32.bf16.bf16.f32 "                       \
        "{%0,%1,%2,%3},{%4,%5,%6,%7},{%8,%9},{%0,%1,%2,%3};"                         \
        : "+f"(d[0]), "+f"(d[1]), "+f"(d[2]), "+f"(d[3])                             \
        : "r"(a[0]), "r"(a[1]), "r"(a[2]), "r"(a[3]), "r"(b[0]), "r"(b[1]))

template <int RELU, int BF16S, int PRE, int OROUND>
__global__ void __launch_bounds__(256)
tf32_gemm_kernel(const float* __restrict__ A, const float* __restrict__ B,
                 const float* __restrict__ bias, float* __restrict__ C,
                 int M, int K, int N) {
    __shared__ __align__(16) float As[2][128][AS_STRIDE];
    __shared__ __align__(16) float Bs[2][16][BS_STRIDE];

    int tid  = threadIdx.x;
    int warp = tid >> 5;
    int lane = tid & 31;
    int gid  = lane >> 2;
    int tq   = lane & 3;
    int wm   = warp >> 2;   // 0..1 -> 64-row slice
    int wn   = warp & 3;    // 0..3 -> 32-col slice

    int bm = blockIdx.y * 128;
    int bn = blockIdx.x * 128;

    float acc[4][4][4];
#pragma unroll
    for (int i = 0; i < 4; i++)
#pragma unroll
        for (int j = 0; j < 4; j++)
#pragma unroll
            for (int r = 0; r < 4; r++) acc[i][j][r] = 0.f;

    int nk = K >> 4;

    const float* Abase = A + (size_t)bm * K;
    const float* Bbase = B + bn;

    auto load_stage = [&](int stage, int k0) {
#pragma unroll
        for (int it = 0; it < 2; it++) {
            int i = tid + it * 256;
            int row = i >> 2, c4 = (i & 3) << 2;
            uint32_t d = (uint32_t)__cvta_generic_to_shared(&As[stage][row][c4]);
            cp16(d, Abase + (size_t)row * K + k0 + c4);
        }
#pragma unroll
        for (int it = 0; it < 2; it++) {
            int i = tid + it * 256;
            int row = i >> 5, c4 = (i & 31) << 2;
            uint32_t d = (uint32_t)__cvta_generic_to_shared(&Bs[stage][row][c4]);
            cp16(d, Bbase + (size_t)(k0 + row) * N + c4);
        }
    };

    load_stage(0, 0);
    asm volatile("cp.async.commit_group;");

    for (int kc = 0; kc < nk; kc++) {
        int cur = kc & 1;
        if (kc + 1 < nk) {
            load_stage(cur ^ 1, (kc + 1) << 4);
            asm volatile("cp.async.commit_group;");
            asm volatile("cp.async.wait_group 1;");
        } else {
            asm volatile("cp.async.wait_group 0;");
        }
        __syncthreads();

        if (BF16S) {
            // ---- bf16 split path: one 16-deep chunk, 3 MMAs per subtile ----
            uint32_t ahi[4][4], alo[4][4], bhi[4][2], blo[4][2];
#pragma unroll
            for (int mt = 0; mt < 4; mt++) {
                int m = wm * 64 + mt * 16;
                float2 q0 = *(const float2*)&As[cur][m + gid][tq * 2];
                float2 q1 = *(const float2*)&As[cur][m + gid + 8][tq * 2];
                float2 q2 = *(const float2*)&As[cur][m + gid][tq * 2 + 8];
                float2 q3 = *(const float2*)&As[cur][m + gid + 8][tq * 2 + 8];
                bf16_split_pack(q0.x, q0.y, ahi[mt][0], alo[mt][0]);
                bf16_split_pack(q1.x, q1.y, ahi[mt][1], alo[mt][1]);
                bf16_split_pack(q2.x, q2.y, ahi[mt][2], alo[mt][2]);
                bf16_split_pack(q3.x, q3.y, ahi[mt][3], alo[mt][3]);
            }
#pragma unroll
            for (int nt = 0; nt < 4; nt++) {
                int n = wn * 32 + nt * 8;
                float u0 = Bs[cur][tq * 2][n + gid];
                float u1 = Bs[cur][tq * 2 + 1][n + gid];
                float u2 = Bs[cur][tq * 2 + 8][n + gid];
                float u3 = Bs[cur][tq * 2 + 9][n + gid];
                bf16_split_pack(u0, u1, bhi[nt][0], blo[nt][0]);
                bf16_split_pack(u2, u3, bhi[nt][1], blo[nt][1]);
            }
#pragma unroll
            for (int mt = 0; mt < 4; mt++)
#pragma unroll
                for (int nt = 0; nt < 4; nt++) {
                    MMA_BF16(acc[mt][nt], ahi[mt], bhi[nt]);
                    MMA_BF16(acc[mt][nt], ahi[mt], blo[nt]);
                    MMA_BF16(acc[mt][nt], alo[mt], bhi[nt]);
                }
        } else {
            // ---- tf32 path (PRE or cvt), two 8-deep halves ----
#pragma unroll
            for (int ks = 0; ks < 16; ks += 8) {
                uint32_t af[4][4], bf[4][2];
#pragma unroll
                for (int mt = 0; mt < 4; mt++) {
                    int m = wm * 64 + mt * 16;
                    float v0 = As[cur][m + gid][ks + tq];
                    float v1 = As[cur][m + gid + 8][ks + tq];
                    float v2 = As[cur][m + gid][ks + tq + 4];
                    float v3 = As[cur][m + gid + 8][ks + tq + 4];
                    if (PRE) {
                        af[mt][0] = __float_as_uint(v0); af[mt][1] = __float_as_uint(v1);
                        af[mt][2] = __float_as_uint(v2); af[mt][3] = __float_as_uint(v3);
                    } else {
                        af[mt][0] = f2tf(v0); af[mt][1] = f2tf(v1);
                        af[mt][2] = f2tf(v2); af[mt][3] = f2tf(v3);
                    }
                }
#pragma unroll
                for (int nt = 0; nt < 4; nt++) {
                    int n = wn * 32 + nt * 8;
                    float u0 = Bs[cur][ks + tq][n + gid];
                    float u1 = Bs[cur][ks + tq + 4][n + gid];
                    if (PRE) {
                        bf[nt][0] = __float_as_uint(u0); bf[nt][1] = __float_as_uint(u1);
                    } else {
                        bf[nt][0] = f2tf(u0); bf[nt][1] = f2tf(u1);
                    }
                }
#pragma unroll
                for (int mt = 0; mt < 4; mt++)
#pragma unroll
                    for (int nt = 0; nt < 4; nt++)
                        MMA_TF32(acc[mt][nt], af[mt], bf[nt]);
            }
        }
        __syncthreads();
    }

    // ---- epilogue: bias (+relu) (+oround), float2 stores ----
#pragma unroll
    for (int mt = 0; mt < 4; mt++) {
        int gr = bm + wm * 64 + mt * 16 + gid;
#pragma unroll
        for (int nt = 0; nt < 4; nt++) {
            int gc = bn + wn * 32 + nt * 8 + tq * 2;
            float2 bv = *(const float2*)&bias[gc];
            float v0 = acc[mt][nt][0] + bv.x;
            float v1 = acc[mt][nt][1] + bv.y;
            float v2 = acc[mt][nt][2] + bv.x;
            float v3 = acc[mt][nt][3] + bv.y;
            if (RELU) {
                v0 = fmaxf(v0, 0.f); v1 = fmaxf(v1, 0.f);
                v2 = fmaxf(v2, 0.f); v3 = fmaxf(v3, 0.f);
            }
            if (OROUND) {
                v0 = __uint_as_float(f2tf(v0)); v1 = __uint_as_float(f2tf(v1));
                v2 = __uint_as_float(f2tf(v2)); v3 = __uint_as_float(f2tf(v3));
            }
            *(float2*)&C[(size_t)gr * N + gc]       = make_float2(v0, v1);
            *(float2*)&C[(size_t)(gr + 8) * N + gc] = make_float2(v2, v3);
        }
    }
}

// ---------------------------------------------------------------------------
// Per-pass gather + L2-normalize.  grid (PP, NGP), block 256.
// ---------------------------------------------------------------------------
__global__ void gather_norm_b_kernel(const float* __restrict__ h2_all,
                                     const int* __restrict__ idx_base,
                                     float* __restrict__ att_out, float* __restrict__ h,
                                     float* __restrict__ h_t, int g) {
    int t = blockIdx.y;
    const int* idx = idx_base + (size_t)t * PP;
    const float* h2 = h2_all + (size_t)t * NP * 256;

    int p = blockIdx.x;
    int f = threadIdx.x;
    int n = idx[p];
    float v = h2[(size_t)n * 256 + f];
    float s = v * v;
    __shared__ float red[8];
    for (int o = 16; o; o >>= 1) s += __shfl_xor_sync(0xffffffffu, s, o);
    if ((f & 31) == 0) red[f >> 5] = s;
    __syncthreads();
    float tot = red[0] + red[1] + red[2] + red[3] + red[4] + red[5] + red[6] + red[7];
    float norm = fmaxf(sqrtf(tot), 1e-12f);
    v /= norm;
    size_t o = ((size_t)(t * PP + p)) * DM + g * 256 + f;
    att_out[o] = v;
    h[o]       = v;
    h_t[o]     = __uint_as_float(f2tf(v));
}

// ---------------------------------------------------------------------------
// Banded attention: window 4, T=16.  One block per (p, head), 128 threads.
// float4 smem fill; output tf32-rounded (feeds PRE Wo GEMM).
// ---------------------------------------------------------------------------
__global__ void attn_kernel(const float* __restrict__ qkv, float* __restrict__ out) {
    int ph = blockIdx.x;
    int p = ph >> 3;
    int h = ph & 7;
    __shared__ float qs[16][64], ks[16][64], vs[16][64];
    int tid = threadIdx.x;
    for (int i = tid; i < 256; i += 128) {
        int t = i >> 4, d4 = (i & 15) << 2;
        const float4* b = (const float4*)(qkv + ((size_t)(t * PP + p)) * 1536 + h * 64 + d4);
        *(float4*)&qs[t][d4] = b[0];
        *(float4*)&ks[t][d4] = b[128];   // +512 floats
        *(float4*)&vs[t][d4] = b[256];   // +1024 floats
    }
    __syncthreads();
    int warp = tid >> 5, lane = tid & 31;
    for (int t = warp; t < 16; t += 4) {
        int s0 = t - 3; if (s0 < 0) s0 = 0;
        int ns = t - s0 + 1;
        float sc[4];
        float mx = -1e30f;
        for (int si = 0; si < ns; si++) {
            int s = s0 + si;
            float d0 = qs[t][lane] * ks[s][lane] + qs[t][lane + 32] * ks[s][lane + 32];
            for (int o = 16; o; o >>= 1) d0 += __shfl_xor_sync(0xffffffffu, d0, o);
            d0 *= 0.125f;
            sc[si] = d0;
            mx = fmaxf(mx, d0);
        }
        float sum = 0.f;
        for (int si = 0; si < ns; si++) { sc[si] = expf(sc[si] - mx); sum += sc[si]; }
        float inv = 1.f / sum;
        float o0 = 0.f, o1 = 0.f;
        for (int si = 0; si < ns; si++) {
            int s = s0 + si;
            o0 += sc[si] * vs[s][lane];
            o1 += sc[si] * vs[s][lane + 32];
        }
        size_t ob = ((size_t)(t * PP + p)) * DM + h * 64;
        out[ob + lane]      = __uint_as_float(f2tf(o0 * inv));
        out[ob + lane + 32] = __uint_as_float(f2tf(o1 * inv));
    }
}

// ---------------------------------------------------------------------------
// h = LayerNorm(h + delta) * g + b; also emits tf32-rounded copy h_t.
// ---------------------------------------------------------------------------
__global__ void resid_ln_kernel(float* __restrict__ h, const float* __restrict__ delta,
                                const float* __restrict__ g, const float* __restrict__ b,
                                float* __restrict__ h_t) {
    int row = blockIdx.x;
    int tid = threadIdx.x;
    size_t base = (size_t)row * DM;
    float v[4];
    float s = 0.f;
#pragma unroll
    for (int i = 0; i < 4; i++) {
        int c = tid + i * 128;
        float x = h[base + c] + delta[base + c];
        v[i] = x; s += x;
    }
    __shared__ float red[4];
    for (int o = 16; o; o >>= 1) s += __shfl_xor_sync(0xffffffffu, s, o);
    if ((tid & 31) == 0) red[tid >> 5] = s;
    __syncthreads();
    float mean = (red[0] + red[1] + red[2] + red[3]) * (1.f / 512.f);
    __syncthreads();
    float s2 = 0.f;
#pragma unroll
    for (int i = 0; i < 4; i++) { float d = v[i] - mean; s2 += d * d; }
    for (int o = 16; o; o >>= 1) s2 += __shfl_xor_sync(0xffffffffu, s2, o);
    if ((tid & 31) == 0) red[tid >> 5] = s2;
    __syncthreads();
    float var = (red[0] + red[1] + red[2] + red[3]) * (1.f / 512.f);
    float rstd = rsqrtf(var + 1e-5f);
#pragma unroll
    for (int i = 0; i < 4; i++) {
        int c = tid + i * 128;
        float o = (v[i] - mean) * rstd * g[c] + b[c];
        h[base + c]   = o;
        h_t[base + c] = __uint_as_float(f2tf(o));
    }
}

// Final projection: out[tok] = h[tok,:] . Wout.  Warp per token.
__global__ void out_kernel(const float* __restrict__ h, const float* __restrict__ W,
                           float* __restrict__ out) {
    int tok = blockIdx.x * 8 + (threadIdx.x >> 5);
    int lane = threadIdx.x & 31;
    const float* r = h + (size_t)tok * DM;
    float s = 0.f;
#pragma unroll
    for (int i = 0; i < 16; i++) s += r[lane + i * 32] * W[lane + i * 32];
    for (int o = 16; o; o >>= 1) s += __shfl_xor_sync(0xffffffffu, s, o);
    if (lane == 0) out[tok] = s;
}

// ---------------------------------------------------------------------------
// Weight prep
// ---------------------------------------------------------------------------
__global__ void prep_wc_kernel(const float* __restrict__ W1s, const float* __restrict__ W1n,
                               const float* __restrict__ W2s, const float* __restrict__ W2n,
                               float* __restrict__ wc1, float* __restrict__ wc2) {
    int i = blockIdx.x * blockDim.x + threadIdx.x;
    if (i < 256 * 256) {
        int k = i >> 8, c = i & 255;
        wc1[i] = (k < 128) ? W1s[k * 256 + c] : W1n[(k - 128) * 256 + c];
    }
    if (i < 512 * 256) {
        int k = i >> 8, c = i & 255;
        wc2[i] = (k < 256) ? W2s[k * 256 + c] : W2n[(k - 256) * 256 + c];
    }
}

__global__ void prep_wqkv_kernel(const float* __restrict__ Wq, const float* __restrict__ Wk,
                                 const float* __restrict__ Wv,
                                 const float* __restrict__ bq, const float* __restrict__ bk,
                                 const float* __restrict__ bv,
                                 float* __restrict__ Wqkv, float* __restrict__ bqkv) {
    int i = blockIdx.x * blockDim.x + threadIdx.x;
    const int tot = 2 * 512 * 1536;
    if (i < tot) {
        int l = i / (512 * 1536);
        int rem = i % (512 * 1536);
        int r = rem / 1536, c = rem % 1536;
        float v;
        size_t wb = (size_t)l * 512 * 512 + (size_t)r * 512;
        if (c < 512)       v = Wq[wb + c];
        else if (c < 1024) v = Wk[wb + (c - 512)];
        else               v = Wv[wb + (c - 1024)];
        Wqkv[i] = __uint_as_float(f2tf(v));
    }
    if (i < 2 * 1536) {
        int l = i / 1536, c = i % 1536;
        float v;
        if (c < 512)       v = bq[l * 512 + c];
        else if (c < 1024) v = bk[l * 512 + c - 512];
        else               v = bv[l * 512 + c - 1024];
        bqkv[i] = v;
    }
}

__global__ void prep_round_kernel(const float* __restrict__ Wo, const float* __restrict__ Wf1,
                                  const float* __restrict__ Wf2,
                                  float* __restrict__ wo_t, float* __restrict__ wf1_t,
                                  float* __restrict__ wf2_t) {
    const int NWO  = 2 * 512 * 512;
    const int NWF1 = 2 * 512 * 2048;
    const int NWF2 = 2 * 2048 * 512;
    int i = blockIdx.x * blockDim.x + threadIdx.x;
    if (i < NWO)  wo_t[i]  = __uint_as_float(f2tf(Wo[i]));
    if (i < NWF1) wf1_t[i] = __uint_as_float(f2tf(Wf1[i]));
    if (i < NWF2) wf2_t[i] = __uint_as_float(f2tf(Wf2[i]));
}

// ---------------------------------------------------------------------------
// Host driver
// ---------------------------------------------------------------------------
extern "C" void kernel_launch(void* const* d_in, const int* in_sizes, int n_in,
                              void* d_out, int out_size) {
    const float* x_i   = (const float*)d_in[0];
    const float* x_j   = (const float*)d_in[1];
    const int*   src_i = (const int*)d_in[2];
    const int*   dst_i = (const int*)d_in[3];
    const int*   src_j = (const int*)d_in[4];
    const int*   dst_j = (const int*)d_in[5];
    const int*   idx_i = (const int*)d_in[6];
    const int*   idx_j = (const int*)d_in[7];
    const float* W1s = (const float*)d_in[8];
    const float* W1n = (const float*)d_in[9];
    const float* b1  = (const float*)d_in[10];
    const float* W2s = (const float*)d_in[11];
    const float* W2n = (const float*)d_in[12];
    const float* b2  = (const float*)d_in[13];
    const float* Wq  = (const float*)d_in[14];
    const float* Wk  = (const float*)d_in[15];
    const float* Wv  = (const float*)d_in[16];
    const float* bq  = (const float*)d_in[17];
    const float* bk  = (const float*)d_in[18];
    const float* bv  = (const float*)d_in[19];
    const float* Wo  = (const float*)d_in[20];
    const float* bo  = (const float*)d_in[21];
    const float* Wf1 = (const float*)d_in[22];
    const float* bf1 = (const float*)d_in[23];
    const float* Wf2 = (const float*)d_in[24];
    const float* bf2 = (const float*)d_in[25];
    const float* g1  = (const float*)d_in[26];
    const float* bg1 = (const float*)d_in[27];
    const float* g2  = (const float*)d_in[28];
    const float* bg2 = (const float*)d_in[29];
    const float* Wout= (const float*)d_in[30];

    void* p;
    cudaGetSymbolAddress(&p, g_sage);  float* SB = (float*)p;
    cudaGetSymbolAddress(&p, g_w);     float* WB = (float*)p;
    cudaGetSymbolAddress(&p, g_act);   float* AB = (float*)p;
    cudaGetSymbolAddress(&p, g_iblob); int*   IB = (int*)p;

    float* h1   = SB + S_H1;
    float* bufB = SB + S_BUFB;
    float* bufA = SB + S_BUFA;
    float* h2   = SB + S_H2;

    float* wc1   = WB + W_WC1;
    float* wc2   = WB + W_WC2;
    float* wqkv  = WB + W_WQKV;
    float* bqkv  = WB + W_BQKV;
    float* wo_t  = WB + W_WO;
    float* wf1_t = WB + W_WF1;
    float* wf2_t = WB + W_WF2;

    float* hbuf = AB + A_H;
    float* h_t  = AB + A_HT;
    float* qkv  = AB + A_QKV;
    float* tmp  = AB + A_TMP;
    float* ffb  = AB + A_FF;

    int* deg  = IB + I_DEG;
    int* cur  = IB + I_CUR;
    int* off  = IB + I_OFF;
    int* csrc = IB + I_CSR;

    float* att_out  = (float*)d_out;
    float* scal_out = att_out + (size_t)NTOK * DM;

    // ---- weight prep ----
    prep_wc_kernel<<<(512 * 256 + 255) / 256, 256>>>(W1s, W1n, W2s, W2n, wc1, wc2);
    prep_wqkv_kernel<<<(2 * 512 * 1536 + 255) / 256, 256>>>(Wq, Wk, Wv, bq, bk, bv, wqkv, bqkv);
    prep_round_kernel<<<(2 * 512 * 2048 + 255) / 256, 256>>>(Wo, Wf1, Wf2, wo_t, wf1_t, wf2_t);

    // ---- batched CSR for all NG graphs ----
    cudaMemsetAsync(IB, 0, (size_t)2 * NG * NN * sizeof(int));   // deg + cur
    hist_b_kernel<<<dim3((EE + 255) / 256, NG), 256>>>(dst_i, dst_j, deg);
    scan_b_kernel<<<NG, 1024>>>(deg, off);
    fill_b_kernel<<<dim3((EE + 255) / 256, NG), 256>>>(src_i, src_j, dst_i, dst_j, off, cur, csrc);

    // ---- batched GraphSAGE, 2 passes (bf16-split tensor GEMMs) ----
    for (int g = 0; g < 2; g++) {
        const float* x   = (g == 0) ? x_i : x_j;
        const int*   idx = (g == 0) ? idx_i : idx_j;
        int gi0 = g * NGP;
        build_A_b_kernel<1><<<dim3(NN, NGP), 128>>>(x, nullptr, 128, off, csrc, bufA, gi0);
        tf32_gemm_kernel<1, 1, 0, 0><<<dim3(2, HB / 128), 256>>>(bufA, wc1, b1, h1, HB, 256, 256);
        build_A_b_kernel<2><<<dim3(NN, NGP), 256>>>(nullptr, h1, 256, off, csrc, bufB, gi0);
        tf32_gemm_kernel<0, 1, 0, 0><<<dim3(2, HB / 128), 256>>>(bufB, wc2, b2, h2, HB, 512, 256);
        gather_norm_b_kernel<<<dim3(PP, NGP), 256>>>(h2, idx, att_out, hbuf, h_t, g);
    }

    // ---- Transformer (PRE tf32 tensor-core GEMMs) ----
    for (int l = 0; l < NLAY; l++) {
        tf32_gemm_kernel<0, 0, 1, 0><<<dim3(12, NTOK / 128), 256>>>(
            h_t, wqkv + (size_t)l * 512 * 1536, bqkv + l * 1536, qkv, NTOK, 512, 1536);
        attn_kernel<<<PP * NHEAD, 128>>>(qkv, tmp);
        tf32_gemm_kernel<0, 0, 1, 0><<<dim3(4, NTOK / 128), 256>>>(
            tmp, wo_t + (size_t)l * 512 * 512, bo + l * 512, ffb, NTOK, 512, 512);
        resid_ln_kernel<<<NTOK, 128>>>(hbuf, ffb, g1 + l * 512, bg1 + l * 512, h_t);
        tf32_gemm_kernel<1, 0, 1, 1><<<dim3(16, NTOK / 128), 256>>>(
            h_t, wf1_t + (size_t)l * 512 * 2048, bf1 + l * 2048, ffb, NTOK, 512, 2048);
        tf32_gemm_kernel<0, 0, 1, 0><<<dim3(4, NTOK / 128), 256>>>(
            ffb, wf2_t + (size_t)l * 2048 * 512, bf2 + l * 512, tmp, NTOK, 2048, 512);
        resid_ln_kernel<<<NTOK, 128>>>(hbuf, tmp, g2 + l * 512, bg2 + l * 512, h_t);
    }

    out_kernel<<<NTOK / 8, 256>>>(hbuf, Wout, scal_out);
}